// round 2
// baseline (speedup 1.0000x reference)
#include <cuda_runtime.h>

// Problem constants
#define B_   2
#define S_   2048
#define DM   1024
#define H_   16
#define DK   64
#define MTOT (B_ * S_)      // 4096
#define NZ   (B_ * H_)      // 32 batched heads

// Scratch (no cudaMalloc allowed): 4 x 16 MB device globals
__device__ float g_qh[(size_t)NZ * S_ * DK];
__device__ float g_kh[(size_t)NZ * S_ * DK];
__device__ float g_vh[(size_t)NZ * S_ * DK];
__device__ float g_ao[(size_t)MTOT * DM];

// ---------------------------------------------------------------------------
// NT GEMM: C = scale * A(MxK, row-major) * B(NxK, row-major)^T
// 128x128x16 tile, 256 threads, 8x8 per-thread microtile.
// OUT_HEAD=1: scatter into [b, h, s, dk] head layout (for Q/K/V projections).
// OUT_HEAD=0: plain row-major [M, N] (scores, output projection).
// Batched via blockIdx.z with per-operand z-strides.
// ---------------------------------------------------------------------------
template <int OUT_HEAD>
__launch_bounds__(256)
__global__ void sgemm_nt(const float* __restrict__ A, const float* __restrict__ Bm,
                         float* __restrict__ C,
                         int N, int K, float scale,
                         long zA, long zB, long zC)
{
    __shared__ float As[16][128];
    __shared__ float Bs[16][128];

    const int z = blockIdx.z;
    A  += (size_t)z * zA;
    Bm += (size_t)z * zB;
    C  += (size_t)z * zC;

    const int m0 = blockIdx.y * 128;
    const int n0 = blockIdx.x * 128;
    const int t  = threadIdx.x;
    const int tm = t >> 4;        // 0..15
    const int tn = t & 15;        // 0..15

    float acc[8][8] = {};

    for (int k0 = 0; k0 < K; k0 += 16) {
        // Load A tile (128x16) and B tile (128x16), transposed into smem.
        // 512 float4 each; 2 per thread.
#pragma unroll
        for (int i = 0; i < 2; i++) {
            int f  = t + i * 256;
            int r  = f >> 2;
            int c4 = (f & 3) << 2;
            float4 va = *(const float4*)&A[(size_t)(m0 + r) * K + k0 + c4];
            As[c4 + 0][r] = va.x; As[c4 + 1][r] = va.y;
            As[c4 + 2][r] = va.z; As[c4 + 3][r] = va.w;
            float4 vb = *(const float4*)&Bm[(size_t)(n0 + r) * K + k0 + c4];
            Bs[c4 + 0][r] = vb.x; Bs[c4 + 1][r] = vb.y;
            Bs[c4 + 2][r] = vb.z; Bs[c4 + 3][r] = vb.w;
        }
        __syncthreads();

#pragma unroll
        for (int kk = 0; kk < 16; kk++) {
            float a[8], b[8];
            *(float4*)(a)     = *(const float4*)&As[kk][tm * 8];
            *(float4*)(a + 4) = *(const float4*)&As[kk][tm * 8 + 4];
            *(float4*)(b)     = *(const float4*)&Bs[kk][tn * 8];
            *(float4*)(b + 4) = *(const float4*)&Bs[kk][tn * 8 + 4];
#pragma unroll
            for (int i = 0; i < 8; i++)
#pragma unroll
                for (int j = 0; j < 8; j++)
                    acc[i][j] += a[i] * b[j];
        }
        __syncthreads();
    }

    // Epilogue (vectorized stores; 8 consecutive n stay inside one head since 8|64)
    const int nb = n0 + tn * 8;
#pragma unroll
    for (int i = 0; i < 8; i++) {
        const int m = m0 + tm * 8 + i;
        float4 lo = make_float4(acc[i][0] * scale, acc[i][1] * scale,
                                acc[i][2] * scale, acc[i][3] * scale);
        float4 hi = make_float4(acc[i][4] * scale, acc[i][5] * scale,
                                acc[i][6] * scale, acc[i][7] * scale);
        float* ptr;
        if (OUT_HEAD) {
            const int b  = m >> 11;          // m / S_
            const int s  = m & (S_ - 1);
            const int h  = nb >> 6;          // n / DK
            const int dk = nb & (DK - 1);
            ptr = C + ((size_t)(b * H_ + h) * S_ + s) * DK + dk;
        } else {
            ptr = C + (size_t)m * N + nb;
        }
        *(float4*)ptr       = lo;
        *(float4*)(ptr + 4) = hi;
    }
}

// ---------------------------------------------------------------------------
// Row softmax, in place. One block per row of 2048 floats; 8 elems/thread,
// fully register-resident, two block reductions (max, sum).
// ---------------------------------------------------------------------------
__launch_bounds__(256)
__global__ void softmax_rows(float* __restrict__ w)
{
    __shared__ float redm[8];
    __shared__ float reds[8];

    float* p = w + (size_t)blockIdx.x * S_;
    const int t = threadIdx.x;

    float4 v0 = ((const float4*)p)[t];
    float4 v1 = ((const float4*)p)[t + 256];

    float mx = fmaxf(fmaxf(fmaxf(v0.x, v0.y), fmaxf(v0.z, v0.w)),
                     fmaxf(fmaxf(v1.x, v1.y), fmaxf(v1.z, v1.w)));
#pragma unroll
    for (int o = 16; o; o >>= 1) mx = fmaxf(mx, __shfl_xor_sync(0xFFFFFFFFu, mx, o));
    if ((t & 31) == 0) redm[t >> 5] = mx;
    __syncthreads();
    mx = redm[0];
#pragma unroll
    for (int i = 1; i < 8; i++) mx = fmaxf(mx, redm[i]);

    v0.x = expf(v0.x - mx); v0.y = expf(v0.y - mx);
    v0.z = expf(v0.z - mx); v0.w = expf(v0.w - mx);
    v1.x = expf(v1.x - mx); v1.y = expf(v1.y - mx);
    v1.z = expf(v1.z - mx); v1.w = expf(v1.w - mx);

    float sm = (v0.x + v0.y + v0.z + v0.w) + (v1.x + v1.y + v1.z + v1.w);
#pragma unroll
    for (int o = 16; o; o >>= 1) sm += __shfl_xor_sync(0xFFFFFFFFu, sm, o);
    if ((t & 31) == 0) reds[t >> 5] = sm;
    __syncthreads();
    sm = reds[0];
#pragma unroll
    for (int i = 1; i < 8; i++) sm += reds[i];

    const float inv = 1.0f / sm;
    v0.x *= inv; v0.y *= inv; v0.z *= inv; v0.w *= inv;
    v1.x *= inv; v1.y *= inv; v1.z *= inv; v1.w *= inv;

    ((float4*)p)[t]       = v0;
    ((float4*)p)[t + 256] = v1;
}

// ---------------------------------------------------------------------------
// PV GEMM (NN): per head z, Ao_part = weights(z)[2048,2048] * Vh(z)[2048,64].
// 64x64x16 tile, 256 threads, 4x4 microtile.
// Writes directly into merged [B, S, H*DK] layout.
// ---------------------------------------------------------------------------
__launch_bounds__(256)
__global__ void sgemm_pv(const float* __restrict__ Wt, const float* __restrict__ Vh,
                         float* __restrict__ Ao)
{
    __shared__ float As[16][64];
    __shared__ float Bs[16][64];

    const int z = blockIdx.z;
    const float* Wz = Wt + (size_t)z * S_ * S_;
    const float* Vz = Vh + (size_t)z * S_ * DK;

    const int m0 = blockIdx.y * 64;
    const int t  = threadIdx.x;
    const int tm = t >> 4;
    const int tn = t & 15;

    float acc[4][4] = {};

    for (int k0 = 0; k0 < S_; k0 += 16) {
        {   // A tile 64x16 (transposed into smem): 256 float4, 1/thread
            int r  = t >> 2;
            int c4 = (t & 3) << 2;
            float4 va = *(const float4*)&Wz[(size_t)(m0 + r) * S_ + k0 + c4];
            As[c4 + 0][r] = va.x; As[c4 + 1][r] = va.y;
            As[c4 + 2][r] = va.z; As[c4 + 3][r] = va.w;
            // B tile 16x64 (direct): 256 float4, 1/thread
            int br  = t >> 4;
            int bc4 = (t & 15) << 2;
            *(float4*)&Bs[br][bc4] = *(const float4*)&Vz[(size_t)(k0 + br) * DK + bc4];
        }
        __syncthreads();

#pragma unroll
        for (int kk = 0; kk < 16; kk++) {
            float a[4], b[4];
            *(float4*)a = *(const float4*)&As[kk][tm * 4];
            *(float4*)b = *(const float4*)&Bs[kk][tn * 4];
#pragma unroll
            for (int i = 0; i < 4; i++)
#pragma unroll
                for (int j = 0; j < 4; j++)
                    acc[i][j] += a[i] * b[j];
        }
        __syncthreads();
    }

    const int bb = z / H_;
    const int h  = z % H_;
#pragma unroll
    for (int i = 0; i < 4; i++) {
        const int qrow = m0 + tm * 4 + i;
        float4 v = make_float4(acc[i][0], acc[i][1], acc[i][2], acc[i][3]);
        *(float4*)&Ao[(size_t)(bb * S_ + qrow) * DM + h * DK + tn * 4] = v;
    }
}

// ---------------------------------------------------------------------------
// Launch: q,k,v,W_q,W_k,W_v,W_o -> (output [B,S,D], attn_weights [B,H,S,S])
// d_out = [output | attn_weights] concatenated, fp32.
// ---------------------------------------------------------------------------
extern "C" void kernel_launch(void* const* d_in, const int* in_sizes, int n_in,
                              void* d_out, int out_size)
{
    const float* q  = (const float*)d_in[0];
    const float* k  = (const float*)d_in[1];
    const float* v  = (const float*)d_in[2];
    const float* Wq = (const float*)d_in[3];
    const float* Wk = (const float*)d_in[4];
    const float* Wv = (const float*)d_in[5];
    const float* Wo = (const float*)d_in[6];

    float* out = (float*)d_out;
    float* wts = out + (size_t)MTOT * DM;   // attn_weights region

    void* p;
    cudaGetSymbolAddress(&p, g_qh); float* qh = (float*)p;
    cudaGetSymbolAddress(&p, g_kh); float* kh = (float*)p;
    cudaGetSymbolAddress(&p, g_vh); float* vh = (float*)p;
    cudaGetSymbolAddress(&p, g_ao); float* ao = (float*)p;

    dim3 blk(256);

    // 1-3) Projections with head-split scatter: [4096,1024] @ [1024,1024]^T
    dim3 gproj(DM / 128, MTOT / 128, 1);
    sgemm_nt<1><<<gproj, blk>>>(q, Wq, qh, DM, DM, 1.0f, 0, 0, 0);
    sgemm_nt<1><<<gproj, blk>>>(k, Wk, kh, DM, DM, 1.0f, 0, 0, 0);
    sgemm_nt<1><<<gproj, blk>>>(v, Wv, vh, DM, DM, 1.0f, 0, 0, 0);

    // 4) Scores: per head, [2048,64] @ [2048,64]^T / 8 -> attn_weights region
    sgemm_nt<0><<<dim3(S_ / 128, S_ / 128, NZ), blk>>>(
        qh, kh, wts, S_, DK, 0.125f,
        (long)S_ * DK, (long)S_ * DK, (long)S_ * S_);

    // 5) Softmax in place over 65536 rows of 2048
    softmax_rows<<<NZ * S_, 256>>>(wts);

    // 6) PV: per head, weights[2048,2048] @ vh[2048,64] -> merged [B,S,1024]
    sgemm_pv<<<dim3(1, S_ / 64, NZ), blk>>>(wts, vh, ao);

    // 7) Output projection: [4096,1024] @ W_o^T -> d_out
    sgemm_nt<0><<<gproj, blk>>>(ao, Wo, out, DM, DM, 1.0f, 0, 0, 0);
}

// round 4
// speedup vs baseline: 2.4856x; 2.4856x over previous
#include <cuda_runtime.h>
#include <cstdint>

// Problem constants
#define B_   2
#define S_   2048
#define DM   1024
#define H_   16
#define DK   64
#define MTOT (B_ * S_)      // 4096
#define NZ   (B_ * H_)      // 32 batched heads

// Scratch (no cudaMalloc allowed)
__device__ float g_qh[(size_t)NZ * S_ * DK];
__device__ float g_kh[(size_t)NZ * S_ * DK];
__device__ float g_vh[(size_t)NZ * S_ * DK];
__device__ float g_ao[(size_t)MTOT * DM];

// fp32 -> tf32 (round-to-nearest) as raw b32
static __device__ __forceinline__ uint32_t f2tf32(float x) {
    uint32_t r;
    asm("cvt.rna.tf32.f32 %0, %1;" : "=r"(r) : "f"(x));
    return r;
}

static __device__ __forceinline__ void mma8(float& d0, float& d1, float& d2, float& d3,
                                            uint32_t a0, uint32_t a1, uint32_t a2, uint32_t a3,
                                            uint32_t b0, uint32_t b1) {
    asm volatile(
        "mma.sync.aligned.m16n8k8.row.col.f32.tf32.tf32.f32 "
        "{%0,%1,%2,%3},{%4,%5,%6,%7},{%8,%9},{%0,%1,%2,%3};"
        : "+f"(d0), "+f"(d1), "+f"(d2), "+f"(d3)
        : "r"(a0), "r"(a1), "r"(a2), "r"(a3), "r"(b0), "r"(b1));
}

// ---------------------------------------------------------------------------
// Tensor-core tf32 GEMM.
//   C = scale * A(MxK, row-major) * B
//   BKMAJ = 0: B is (N x K) row-major, C = A*B^T   (NT; projections/scores/o-proj)
//   BKMAJ = 1: B is (K x N) row-major, C = A*B     (NN; PV, uses vh natively)
// Block tile 128 x BN x 32, 256 threads = 8 warps in 4(m) x 2(n).
// Warp tile 32 x BN/2 -> m16n8k8 frags: 2 (m) x BN/16 (n).
// OUTMODE: 0 plain row-major [*, ldc]; 1 head scatter [b,h,s,dk]; 2 PV merge.
// ---------------------------------------------------------------------------
template <int BKMAJ, int OUTMODE, int BN>
__launch_bounds__(256, 2)
__global__ void tgemm(const float* __restrict__ A, const float* __restrict__ Bm,
                      float* __restrict__ C,
                      int K, int ldb, int ldc, float scale,
                      long zA, long zB, long zC)
{
    constexpr int NFRAG = BN / 16;           // n-frags per warp
    constexpr int BSTR  = BKMAJ ? (BN + 8) : 36;

    __shared__ uint32_t As[128 * 36];
    __shared__ uint32_t Bs[BKMAJ ? 32 * (BN + 8) : BN * 36];

    const int z = blockIdx.z;
    A  += (size_t)z * zA;
    Bm += (size_t)z * zB;

    const int m0   = blockIdx.y * 128;
    const int n0   = blockIdx.x * BN;
    const int t    = threadIdx.x;
    const int lane = t & 31;
    const int warp = t >> 5;
    const int wm0  = (warp >> 1) * 32;
    const int wn0  = (warp & 1) * (BN / 2);
    const int lr   = lane >> 2;      // 0..7
    const int lc   = lane & 3;       // 0..3

    float acc[2][NFRAG][4] = {};

    for (int k0 = 0; k0 < K; k0 += 32) {
        __syncthreads();
        // A tile: 128 x 32, cvt to tf32, [m][k] stride 36 (conflict-free frag reads)
#pragma unroll
        for (int i = 0; i < 4; i++) {
            int f = t + i * 256, r = f >> 3, c4 = (f & 7) << 2;
            float4 v = *(const float4*)&A[(size_t)(m0 + r) * K + k0 + c4];
            uint4 u = make_uint4(f2tf32(v.x), f2tf32(v.y), f2tf32(v.z), f2tf32(v.w));
            *(uint4*)&As[r * 36 + c4] = u;
        }
        if (!BKMAJ) {
            // B tile: BN x 32 (n-major rows), [n][k] stride 36
#pragma unroll
            for (int i = 0; i < BN / 32; i++) {
                int f = t + i * 256, r = f >> 3, c4 = (f & 7) << 2;
                float4 v = *(const float4*)&Bm[(size_t)(n0 + r) * ldb + k0 + c4];
                uint4 u = make_uint4(f2tf32(v.x), f2tf32(v.y), f2tf32(v.z), f2tf32(v.w));
                *(uint4*)&Bs[r * 36 + c4] = u;
            }
        } else {
            // B tile: 32(k) x BN, [k][n] stride BN+8
#pragma unroll
            for (int i = 0; i < BN / 32; i++) {
                int f = t + i * 256, kr = f >> 4, c4 = (f & 15) << 2;
                float4 v = *(const float4*)&Bm[(size_t)(k0 + kr) * ldb + n0 + c4];
                uint4 u = make_uint4(f2tf32(v.x), f2tf32(v.y), f2tf32(v.z), f2tf32(v.w));
                *(uint4*)&Bs[kr * BSTR + c4] = u;
            }
        }
        __syncthreads();

#pragma unroll
        for (int k8 = 0; k8 < 4; k8++) {
            const int kc = k8 * 8 + lc;
            uint32_t bf[NFRAG][2];
#pragma unroll
            for (int nf = 0; nf < NFRAG; nf++) {
                int n = wn0 + nf * 8 + lr;
                if (!BKMAJ) {
                    bf[nf][0] = Bs[n * 36 + kc];
                    bf[nf][1] = Bs[n * 36 + kc + 4];
                } else {
                    bf[nf][0] = Bs[kc * BSTR + n];
                    bf[nf][1] = Bs[(kc + 4) * BSTR + n];
                }
            }
#pragma unroll
            for (int mf = 0; mf < 2; mf++) {
                int r = wm0 + mf * 16 + lr;
                uint32_t a0 = As[r * 36 + kc];
                uint32_t a1 = As[(r + 8) * 36 + kc];
                uint32_t a2 = As[r * 36 + kc + 4];
                uint32_t a3 = As[(r + 8) * 36 + kc + 4];
#pragma unroll
                for (int nf = 0; nf < NFRAG; nf++)
                    mma8(acc[mf][nf][0], acc[mf][nf][1], acc[mf][nf][2], acc[mf][nf][3],
                         a0, a1, a2, a3, bf[nf][0], bf[nf][1]);
            }
        }
    }

    // Epilogue
#pragma unroll
    for (int mf = 0; mf < 2; mf++) {
        const int r0 = m0 + wm0 + mf * 16 + lr;
#pragma unroll
        for (int nf = 0; nf < NFRAG; nf++) {
            const int c = n0 + wn0 + nf * 8 + 2 * lc;
            float2 lo = make_float2(acc[mf][nf][0] * scale, acc[mf][nf][1] * scale);
            float2 hi = make_float2(acc[mf][nf][2] * scale, acc[mf][nf][3] * scale);
#pragma unroll
            for (int half = 0; half < 2; half++) {
                const int r = r0 + half * 8;
                float* ptr;
                if (OUTMODE == 0) {
                    ptr = C + (size_t)z * zC + (size_t)r * ldc + c;
                } else if (OUTMODE == 1) {
                    const int b  = r >> 11;          // r / S_
                    const int s  = r & (S_ - 1);
                    const int h  = c >> 6;           // c / DK
                    const int dk = c & (DK - 1);
                    ptr = C + ((size_t)(b * H_ + h) * S_ + s) * DK + dk;
                } else {                              // PV merge -> [B, S, DM]
                    const int bb = z / H_;
                    const int h  = z % H_;
                    ptr = C + ((size_t)(bb * S_ + r)) * DM + h * DK + c;
                }
                *(float2*)ptr = half ? hi : lo;
            }
        }
    }
}

// ---------------------------------------------------------------------------
// Row softmax, in place. One block per row of 2048 floats.
// ---------------------------------------------------------------------------
__launch_bounds__(256)
__global__ void softmax_rows(float* __restrict__ w)
{
    __shared__ float redm[8];
    __shared__ float reds[8];

    float* p = w + (size_t)blockIdx.x * S_;
    const int t = threadIdx.x;

    float4 v0 = ((const float4*)p)[t];
    float4 v1 = ((const float4*)p)[t + 256];

    float mx = fmaxf(fmaxf(fmaxf(v0.x, v0.y), fmaxf(v0.z, v0.w)),
                     fmaxf(fmaxf(v1.x, v1.y), fmaxf(v1.z, v1.w)));
#pragma unroll
    for (int o = 16; o; o >>= 1) mx = fmaxf(mx, __shfl_xor_sync(0xFFFFFFFFu, mx, o));
    if ((t & 31) == 0) redm[t >> 5] = mx;
    __syncthreads();
    mx = redm[0];
#pragma unroll
    for (int i = 1; i < 8; i++) mx = fmaxf(mx, redm[i]);

    v0.x = expf(v0.x - mx); v0.y = expf(v0.y - mx);
    v0.z = expf(v0.z - mx); v0.w = expf(v0.w - mx);
    v1.x = expf(v1.x - mx); v1.y = expf(v1.y - mx);
    v1.z = expf(v1.z - mx); v1.w = expf(v1.w - mx);

    float sm = (v0.x + v0.y + v0.z + v0.w) + (v1.x + v1.y + v1.z + v1.w);
#pragma unroll
    for (int o = 16; o; o >>= 1) sm += __shfl_xor_sync(0xFFFFFFFFu, sm, o);
    if ((t & 31) == 0) reds[t >> 5] = sm;
    __syncthreads();
    sm = reds[0];
#pragma unroll
    for (int i = 1; i < 8; i++) sm += reds[i];

    const float inv = 1.0f / sm;
    v0.x *= inv; v0.y *= inv; v0.z *= inv; v0.w *= inv;
    v1.x *= inv; v1.y *= inv; v1.z *= inv; v1.w *= inv;

    ((float4*)p)[t]       = v0;
    ((float4*)p)[t + 256] = v1;
}

// ---------------------------------------------------------------------------
extern "C" void kernel_launch(void* const* d_in, const int* in_sizes, int n_in,
                              void* d_out, int out_size)
{
    (void)in_sizes; (void)n_in; (void)out_size;
    const float* q  = (const float*)d_in[0];
    const float* k  = (const float*)d_in[1];
    const float* v  = (const float*)d_in[2];
    const float* Wq = (const float*)d_in[3];
    const float* Wk = (const float*)d_in[4];
    const float* Wv = (const float*)d_in[5];
    const float* Wo = (const float*)d_in[6];

    float* out = (float*)d_out;
    float* wts = out + (size_t)MTOT * DM;   // attn_weights region

    void* p;
    cudaGetSymbolAddress(&p, g_qh); float* qh = (float*)p;
    cudaGetSymbolAddress(&p, g_kh); float* kh = (float*)p;
    cudaGetSymbolAddress(&p, g_vh); float* vh = (float*)p;
    cudaGetSymbolAddress(&p, g_ao); float* ao = (float*)p;

    dim3 blk(256);

    // 1-3) Projections: [4096,1024] @ W^T, head-split scatter into [b,h,s,dk]
    dim3 gproj(DM / 128, MTOT / 128, 1);
    tgemm<0, 1, 128><<<gproj, blk>>>(q, Wq, qh, DM, DM, 0, 1.0f, 0, 0, 0);
    tgemm<0, 1, 128><<<gproj, blk>>>(k, Wk, kh, DM, DM, 0, 1.0f, 0, 0, 0);
    tgemm<0, 1, 128><<<gproj, blk>>>(v, Wv, vh, DM, DM, 0, 1.0f, 0, 0, 0);

    // 4) Scores: per head, qh[2048,64] @ kh^T / 8 -> attn_weights region
    tgemm<0, 0, 128><<<dim3(S_ / 128, S_ / 128, NZ), blk>>>(
        qh, kh, wts, DK, DK, S_, 0.125f,
        (long)S_ * DK, (long)S_ * DK, (long)S_ * S_);

    // 5) Softmax in place over 65536 rows of 2048
    softmax_rows<<<NZ * S_, 256>>>(wts);

    // 6) PV (NN): per head, wts[2048,2048] @ vh[2048,64] -> merged [B,S,1024]
    tgemm<1, 2, 64><<<dim3(1, S_ / 128, NZ), blk>>>(
        wts, vh, ao, S_, DK, 0, 1.0f,
        (long)S_ * S_, (long)S_ * DK, 0);

    // 7) Output projection: [4096,1024] @ W_o^T -> d_out
    tgemm<0, 0, 128><<<gproj, blk>>>(ao, Wo, out, DM, DM, DM, 1.0f, 0, 0, 0);
}